// round 2
// baseline (speedup 1.0000x reference)
#include <cuda_runtime.h>
#include <math.h>

// ---------------------------------------------------------------------------
// GooseRecurrentLayer: LN -> token-shift mix -> {k,v,r} GEMMs -> channel-wise
// linear recurrence -> output GEMM with residual.
//
// Shapes: x (8, 2048, 1024); all weights (1024, 1024) row-major (E, D),
// out[., e] = sum_d in[., d] * W[e, d].
//
// d_out layout (flattened reference tuple, fp32):
//   [0, 16777216)             out      (B, T, D)
//   [16777216, 16785408)      final_S  (B, D)
//   [16785408, 33562624)      S_seq    (B, T, D)
// ---------------------------------------------------------------------------

#define D_MODEL 1024
#define BATCH   8
#define SEQ     2048
#define M_ROWS  (BATCH * SEQ)        // 16384
#define LN_EPS  1e-5f

// Scratch (device globals: allocation-free rule).
__device__ float g_xk[(size_t)M_ROWS * D_MODEL];
__device__ float g_xv[(size_t)M_ROWS * D_MODEL];
__device__ float g_xr[(size_t)M_ROWS * D_MODEL];
__device__ float g_k [(size_t)M_ROWS * D_MODEL];
__device__ float g_v [(size_t)M_ROWS * D_MODEL];
__device__ float g_r [(size_t)M_ROWS * D_MODEL];

// ---------------------------------------------------------------------------
// Kernel 1: LayerNorm of row t and row t-1 (recomputed; cheap) + token mix.
// One block (256 threads) per (b, t) row; each thread owns one float4.
// ---------------------------------------------------------------------------
__inline__ __device__ float warp_sum(float v) {
#pragma unroll
    for (int o = 16; o > 0; o >>= 1) v += __shfl_xor_sync(0xffffffffu, v, o);
    return v;
}

__global__ __launch_bounds__(256)
void prep_kernel(const float* __restrict__ x,
                 const float* __restrict__ ln_w,
                 const float* __restrict__ ln_b,
                 const float* __restrict__ tmk,
                 const float* __restrict__ tmv,
                 const float* __restrict__ tmr) {
    const int row = blockIdx.x;          // 0 .. M_ROWS-1
    const int t   = row & (SEQ - 1);
    const int tid = threadIdx.x;

    const float4* xc = (const float4*)(x + (size_t)row * D_MODEL);
    float4 c = xc[tid];
    float4 p = make_float4(0.f, 0.f, 0.f, 0.f);
    if (t > 0) {
        const float4* xp = (const float4*)(x + (size_t)(row - 1) * D_MODEL);
        p = xp[tid];
    }

    float sc  = c.x + c.y + c.z + c.w;
    float sc2 = c.x * c.x + c.y * c.y + c.z * c.z + c.w * c.w;
    float sp  = p.x + p.y + p.z + p.w;
    float sp2 = p.x * p.x + p.y * p.y + p.z * p.z + p.w * p.w;

    sc  = warp_sum(sc);  sc2 = warp_sum(sc2);
    sp  = warp_sum(sp);  sp2 = warp_sum(sp2);

    __shared__ float sm[4][8];
    __shared__ float stats[4];
    const int warp = tid >> 5, lane = tid & 31;
    if (lane == 0) { sm[0][warp] = sc; sm[1][warp] = sc2; sm[2][warp] = sp; sm[3][warp] = sp2; }
    __syncthreads();
    if (tid < 4) {
        float s = 0.f;
#pragma unroll
        for (int w = 0; w < 8; w++) s += sm[tid][w];
        stats[tid] = s;
    }
    __syncthreads();

    const float inv_n = 1.0f / (float)D_MODEL;
    const float mc = stats[0] * inv_n;
    const float vc = stats[1] * inv_n - mc * mc;
    const float rc = rsqrtf(vc + LN_EPS);
    const float mp = stats[2] * inv_n;
    const float vp = stats[3] * inv_n - mp * mp;
    const float rp = rsqrtf(vp + LN_EPS);
    const bool has_prev = (t > 0);

    const float4 w4 = ((const float4*)ln_w)[tid];
    const float4 b4 = ((const float4*)ln_b)[tid];
    const float4 k4 = ((const float4*)tmk)[tid];
    const float4 v4 = ((const float4*)tmv)[tid];
    const float4 r4 = ((const float4*)tmr)[tid];

    float cn[4], pn[4];
    const float cv[4] = {c.x, c.y, c.z, c.w};
    const float pv[4] = {p.x, p.y, p.z, p.w};
    const float wv[4] = {w4.x, w4.y, w4.z, w4.w};
    const float bv[4] = {b4.x, b4.y, b4.z, b4.w};
#pragma unroll
    for (int i = 0; i < 4; i++) {
        cn[i] = (cv[i] - mc) * rc * wv[i] + bv[i];
        pn[i] = has_prev ? ((pv[i] - mp) * rp * wv[i] + bv[i]) : 0.f;
    }

    const float kk[4]  = {k4.x, k4.y, k4.z, k4.w};
    const float vvv[4] = {v4.x, v4.y, v4.z, v4.w};
    const float rr[4]  = {r4.x, r4.y, r4.z, r4.w};
    float4 ok, ov, orr;
    float* okp = (float*)&ok; float* ovp = (float*)&ov; float* orp = (float*)&orr;
#pragma unroll
    for (int i = 0; i < 4; i++) {
        okp[i] = cn[i] * kk[i]  + pn[i] * (1.0f - kk[i]);
        ovp[i] = cn[i] * vvv[i] + pn[i] * (1.0f - vvv[i]);
        orp[i] = cn[i] * rr[i]  + pn[i] * (1.0f - rr[i]);
    }
    const size_t off = (size_t)row * D_MODEL;
    ((float4*)(g_xk + off))[tid] = ok;
    ((float4*)(g_xv + off))[tid] = ov;
    ((float4*)(g_xr + off))[tid] = orr;
}

// ---------------------------------------------------------------------------
// Tiled fp32 SGEMM body.  C[m,n] = sum_k A[m,k] * W[n,k]
//   A row-major (M x K), W row-major (N x K); K = N = 1024, M = 16384.
// MODE 0: C = acc ; MODE 1: C = sigmoid(acc) ; MODE 2: C = aux_x + aux_r*acc
// BM=BN=128, BK=16, 256 threads, 8x8 per thread.
// +8-float padding keeps fragment rows 16B-aligned -> LDS.128.
// Register-staged prefetch overlaps next tile's LDGs with current compute.
// ---------------------------------------------------------------------------
template <int MODE>
__device__ __forceinline__
void sgemm_body(const float* __restrict__ A, const float* __restrict__ W,
                float* __restrict__ C,
                const float* __restrict__ aux_r, const float* __restrict__ aux_x,
                int m0, int n0) {
    constexpr int BM = 128, BN = 128, BK = 16, PAD = 8;
    __shared__ float As[BK][BM + PAD];
    __shared__ float Bs[BK][BN + PAD];

    const int tid = threadIdx.x;
    const int tx = tid & 15;       // 0..15  -> n
    const int ty = tid >> 4;       // 0..15  -> m
    const int K = D_MODEL;

    // Load mapping: idx = tid + i*256 in [0,512); r = idx>>2 row, kq = (idx&3)*4.
    const int r0  = tid >> 2;            // 0..63
    const int kq0 = (tid & 3) << 2;      // 0,4,8,12

    float acc[8][8];
#pragma unroll
    for (int i = 0; i < 8; i++)
#pragma unroll
        for (int j = 0; j < 8; j++) acc[i][j] = 0.f;

    float4 a_reg[2], b_reg[2];

    // prefetch tile 0
#pragma unroll
    for (int i = 0; i < 2; i++) {
        const int r = r0 + i * 64;
        a_reg[i] = *(const float4*)(A + (size_t)(m0 + r) * K + kq0);
        b_reg[i] = *(const float4*)(W + (size_t)(n0 + r) * K + kq0);
    }

    for (int k0 = 0; k0 < K; k0 += BK) {
        // stage registers -> smem (previous compute finished at loop-tail sync)
#pragma unroll
        for (int i = 0; i < 2; i++) {
            const int r = r0 + i * 64;
            As[kq0 + 0][r] = a_reg[i].x; As[kq0 + 1][r] = a_reg[i].y;
            As[kq0 + 2][r] = a_reg[i].z; As[kq0 + 3][r] = a_reg[i].w;
            Bs[kq0 + 0][r] = b_reg[i].x; Bs[kq0 + 1][r] = b_reg[i].y;
            Bs[kq0 + 2][r] = b_reg[i].z; Bs[kq0 + 3][r] = b_reg[i].w;
        }
        __syncthreads();

        // prefetch next tile while computing this one
        if (k0 + BK < K) {
#pragma unroll
            for (int i = 0; i < 2; i++) {
                const int r = r0 + i * 64;
                a_reg[i] = *(const float4*)(A + (size_t)(m0 + r) * K + k0 + BK + kq0);
                b_reg[i] = *(const float4*)(W + (size_t)(n0 + r) * K + k0 + BK + kq0);
            }
        }

#pragma unroll
        for (int k = 0; k < BK; k++) {
            const float4 a0 = *(const float4*)&As[k][ty * 8];
            const float4 a1 = *(const float4*)&As[k][ty * 8 + 4];
            const float4 b0 = *(const float4*)&Bs[k][tx * 8];
            const float4 b1 = *(const float4*)&Bs[k][tx * 8 + 4];
            const float af[8] = {a0.x, a0.y, a0.z, a0.w, a1.x, a1.y, a1.z, a1.w};
            const float bf[8] = {b0.x, b0.y, b0.z, b0.w, b1.x, b1.y, b1.z, b1.w};
#pragma unroll
            for (int i = 0; i < 8; i++)
#pragma unroll
                for (int j = 0; j < 8; j++)
                    acc[i][j] = fmaf(af[i], bf[j], acc[i][j]);
        }
        __syncthreads();
    }

#pragma unroll
    for (int i = 0; i < 8; i++) {
        const int m = m0 + ty * 8 + i;
#pragma unroll
        for (int j = 0; j < 8; j += 4) {
            const int n = n0 + tx * 8 + j;
            const size_t idx = (size_t)m * D_MODEL + n;
            float4 o = make_float4(acc[i][j], acc[i][j + 1], acc[i][j + 2], acc[i][j + 3]);
            if (MODE == 1) {
                o.x = 1.0f / (1.0f + expf(-o.x));
                o.y = 1.0f / (1.0f + expf(-o.y));
                o.z = 1.0f / (1.0f + expf(-o.z));
                o.w = 1.0f / (1.0f + expf(-o.w));
            } else if (MODE == 2) {
                const float4 rr = *(const float4*)(aux_r + idx);
                const float4 xx = *(const float4*)(aux_x + idx);
                o.x = xx.x + rr.x * o.x;
                o.y = xx.y + rr.y * o.y;
                o.z = xx.z + rr.z * o.z;
                o.w = xx.w + rr.w * o.w;
            }
            *(float4*)(C + idx) = o;
        }
    }
}

// Fused k/v/r projection: blockIdx.z selects which GEMM; z==2 applies sigmoid.
__global__ __launch_bounds__(256)
void proj_kvr_kernel(const float* __restrict__ xk, const float* __restrict__ Wk, float* __restrict__ ok,
                     const float* __restrict__ xv, const float* __restrict__ Wv, float* __restrict__ ov,
                     const float* __restrict__ xr, const float* __restrict__ Wr, float* __restrict__ orr) {
    const int m0 = blockIdx.y * 128;
    const int n0 = blockIdx.x * 128;
    if (blockIdx.z == 0)      sgemm_body<0>(xk, Wk, ok,  nullptr, nullptr, m0, n0);
    else if (blockIdx.z == 1) sgemm_body<0>(xv, Wv, ov,  nullptr, nullptr, m0, n0);
    else                      sgemm_body<1>(xr, Wr, orr, nullptr, nullptr, m0, n0);
}

// Output GEMM: out = x + r * (S_seq @ Wo^T)
__global__ __launch_bounds__(256)
void out_gemm_kernel(const float* __restrict__ S, const float* __restrict__ Wo,
                     float* __restrict__ out,
                     const float* __restrict__ r, const float* __restrict__ x) {
    sgemm_body<2>(S, Wo, out, r, x, blockIdx.y * 128, blockIdx.x * 128);
}

// ---------------------------------------------------------------------------
// Kernel 3: channel-wise linear recurrence.
//   S[b,t,d] = decay[d] * S[b,t-1,d] + k[b,t,d] * v[b,t,d]
// One thread per (b, d): 8192 threads. Unrolled x4 for MLP.
// ---------------------------------------------------------------------------
__global__ __launch_bounds__(256)
void scan_kernel(const float* __restrict__ gk, const float* __restrict__ gv,
                 const float* __restrict__ decay_w,
                 float* __restrict__ S_seq, float* __restrict__ final_S) {
    const int gid = blockIdx.x * blockDim.x + threadIdx.x;
    if (gid >= BATCH * D_MODEL) return;
    const int b = gid >> 10;
    const int d = gid & 1023;
    const float dec = 1.0f / (1.0f + expf(-decay_w[d]));
    float S = 0.f;
    size_t base = ((size_t)b * SEQ) * D_MODEL + d;
    for (int t = 0; t < SEQ; t += 4) {
        const float kv0 = gk[base]               * gv[base];
        const float kv1 = gk[base +     D_MODEL] * gv[base +     D_MODEL];
        const float kv2 = gk[base + 2 * D_MODEL] * gv[base + 2 * D_MODEL];
        const float kv3 = gk[base + 3 * D_MODEL] * gv[base + 3 * D_MODEL];
        S = fmaf(dec, S, kv0); S_seq[base]               = S;
        S = fmaf(dec, S, kv1); S_seq[base +     D_MODEL] = S;
        S = fmaf(dec, S, kv2); S_seq[base + 2 * D_MODEL] = S;
        S = fmaf(dec, S, kv3); S_seq[base + 3 * D_MODEL] = S;
        base += 4 * (size_t)D_MODEL;
    }
    final_S[gid] = S;
}

// ---------------------------------------------------------------------------
extern "C" void kernel_launch(void* const* d_in, const int* in_sizes, int n_in,
                              void* d_out, int out_size) {
    const float* x       = (const float*)d_in[0];
    const float* ln_w    = (const float*)d_in[1];
    const float* ln_b    = (const float*)d_in[2];
    const float* tmk     = (const float*)d_in[3];
    const float* tmv     = (const float*)d_in[4];
    const float* tmr     = (const float*)d_in[5];
    const float* decay_w = (const float*)d_in[6];
    const float* Wk      = (const float*)d_in[7];
    const float* Wv      = (const float*)d_in[8];
    const float* Wr      = (const float*)d_in[9];
    const float* Wo      = (const float*)d_in[10];

    float* out     = (float*)d_out;
    float* final_S = out + (size_t)M_ROWS * D_MODEL;
    float* S_seq   = final_S + (size_t)BATCH * D_MODEL;

    // Symbol addresses for scratch (host side; capture-safe, no stream work).
    float *p_xk, *p_xv, *p_xr, *p_k, *p_v, *p_r;
    cudaGetSymbolAddress((void**)&p_xk, g_xk);
    cudaGetSymbolAddress((void**)&p_xv, g_xv);
    cudaGetSymbolAddress((void**)&p_xr, g_xr);
    cudaGetSymbolAddress((void**)&p_k,  g_k);
    cudaGetSymbolAddress((void**)&p_v,  g_v);
    cudaGetSymbolAddress((void**)&p_r,  g_r);

    // 1) LN + token mix
    prep_kernel<<<M_ROWS, 256>>>(x, ln_w, ln_b, tmk, tmv, tmr);

    // 2) k, v, r projections (fused launch: z selects GEMM)
    dim3 gkvr(D_MODEL / 128, M_ROWS / 128, 3);
    proj_kvr_kernel<<<gkvr, 256>>>(p_xk, Wk, p_k, p_xv, Wv, p_v, p_xr, Wr, p_r);

    // 3) recurrence -> S_seq (directly into d_out) + final_S
    scan_kernel<<<(BATCH * D_MODEL) / 256, 256>>>(p_k, p_v, decay_w, S_seq, final_S);

    // 4) out = x + r * (S_seq @ Wo^T)
    dim3 gout(D_MODEL / 128, M_ROWS / 128);
    out_gemm_kernel<<<gout, 256>>>(S_seq, Wo, out, p_r, x);
}

// round 10
// speedup vs baseline: 1.7429x; 1.7429x over previous
#include <cuda_runtime.h>
#include <cuda_bf16.h>
#include <math.h>
#include <stdint.h>

// ---------------------------------------------------------------------------
// GooseRecurrentLayer on GB300 — tensor-core (bf16 split-3) GEMM path.
//
// out[., e] = x + r * (S_seq @ Wo^T);  k/v/r = (mix @ W^T); S = scan(decay, k*v)
//
// fp32 emulated on bf16 tensor cores: A = Ah + Al (bf16 hi/lo split),
// A.B ~= Ah.Bh + Ah.Bl + Al.Bh  (fp32 accumulate)  -> ~1e-5 rel err.
//
// d_out layout (flattened reference tuple, fp32):
//   [0, 16777216)             out      (B, T, D)
//   [16777216, 16785408)      final_S  (B, D)
//   [16785408, 33562624)      S_seq    (B, T, D)
// ---------------------------------------------------------------------------

#define D_MODEL 1024
#define BATCH   8
#define SEQ     2048
#define M_ROWS  (BATCH * SEQ)        // 16384
#define LN_EPS  1e-5f
#define MD      ((size_t)M_ROWS * D_MODEL)

// Scratch (device globals: allocation-free rule).
__device__ __nv_bfloat16 g_xk_h[MD], g_xk_l[MD];
__device__ __nv_bfloat16 g_xv_h[MD], g_xv_l[MD];
__device__ __nv_bfloat16 g_xr_h[MD], g_xr_l[MD];
__device__ float         g_k[MD], g_v[MD], g_r[MD];
__device__ __nv_bfloat16 g_S_h[MD], g_S_l[MD];
__device__ __nv_bfloat16 g_W_h[(size_t)4 * D_MODEL * D_MODEL];
__device__ __nv_bfloat16 g_W_l[(size_t)4 * D_MODEL * D_MODEL];

// ---------------------------------------------------------------------------
// helpers
// ---------------------------------------------------------------------------
__device__ __forceinline__ float warp_sum(float v) {
#pragma unroll
    for (int o = 16; o > 0; o >>= 1) v += __shfl_xor_sync(0xffffffffu, v, o);
    return v;
}

__device__ __forceinline__ void split_bf16(float x, unsigned short& h, unsigned short& l) {
    __nv_bfloat16 hh = __float2bfloat16(x);
    __nv_bfloat16 ll = __float2bfloat16(x - __bfloat162float(hh));
    h = __bfloat16_as_ushort(hh);
    l = __bfloat16_as_ushort(ll);
}

__device__ __forceinline__ void ldsm4(uint32_t* r, uint32_t addr) {
    asm volatile("ldmatrix.sync.aligned.m8n8.x4.shared.b16 {%0,%1,%2,%3}, [%4];"
                 : "=r"(r[0]), "=r"(r[1]), "=r"(r[2]), "=r"(r[3]) : "r"(addr));
}

__device__ __forceinline__ void mma16816(float* c, const uint32_t* a, uint32_t b0, uint32_t b1) {
    asm volatile("mma.sync.aligned.m16n8k16.row.col.f32.bf16.bf16.f32 "
                 "{%0,%1,%2,%3}, {%4,%5,%6,%7}, {%8,%9}, {%0,%1,%2,%3};"
                 : "+f"(c[0]), "+f"(c[1]), "+f"(c[2]), "+f"(c[3])
                 : "r"(a[0]), "r"(a[1]), "r"(a[2]), "r"(a[3]), "r"(b0), "r"(b1));
}

__device__ __forceinline__ void cp16(uint32_t saddr, const void* gaddr) {
    asm volatile("cp.async.ca.shared.global [%0], [%1], 16;" :: "r"(saddr), "l"(gaddr));
}

// ---------------------------------------------------------------------------
// Kernel 1: LayerNorm(t) + LayerNorm(t-1) + token mix -> bf16 hi/lo splits.
// One block (256 threads) per row; each thread owns one float4.
// ---------------------------------------------------------------------------
__global__ __launch_bounds__(256)
void prep_kernel(const float* __restrict__ x,
                 const float* __restrict__ ln_w, const float* __restrict__ ln_b,
                 const float* __restrict__ tmk, const float* __restrict__ tmv,
                 const float* __restrict__ tmr) {
    const int row = blockIdx.x;
    const int t   = row & (SEQ - 1);
    const int tid = threadIdx.x;

    float4 c = ((const float4*)(x + (size_t)row * D_MODEL))[tid];
    float4 p = make_float4(0.f, 0.f, 0.f, 0.f);
    if (t > 0) p = ((const float4*)(x + (size_t)(row - 1) * D_MODEL))[tid];

    float sc  = c.x + c.y + c.z + c.w;
    float sc2 = c.x * c.x + c.y * c.y + c.z * c.z + c.w * c.w;
    float sp  = p.x + p.y + p.z + p.w;
    float sp2 = p.x * p.x + p.y * p.y + p.z * p.z + p.w * p.w;
    sc = warp_sum(sc); sc2 = warp_sum(sc2); sp = warp_sum(sp); sp2 = warp_sum(sp2);

    __shared__ float sm[4][8];
    __shared__ float stats[4];
    const int warp = tid >> 5, lane = tid & 31;
    if (lane == 0) { sm[0][warp] = sc; sm[1][warp] = sc2; sm[2][warp] = sp; sm[3][warp] = sp2; }
    __syncthreads();
    if (tid < 4) {
        float s = 0.f;
#pragma unroll
        for (int w = 0; w < 8; w++) s += sm[tid][w];
        stats[tid] = s;
    }
    __syncthreads();

    const float inv_n = 1.0f / (float)D_MODEL;
    const float mc = stats[0] * inv_n;
    const float rc = rsqrtf(stats[1] * inv_n - mc * mc + LN_EPS);
    const float mp = stats[2] * inv_n;
    const float rp = rsqrtf(stats[3] * inv_n - mp * mp + LN_EPS);
    const bool has_prev = (t > 0);

    const float4 w4 = ((const float4*)ln_w)[tid];
    const float4 b4 = ((const float4*)ln_b)[tid];
    const float4 k4 = ((const float4*)tmk)[tid];
    const float4 v4 = ((const float4*)tmv)[tid];
    const float4 r4 = ((const float4*)tmr)[tid];

    const float cv[4] = {c.x, c.y, c.z, c.w};
    const float pv[4] = {p.x, p.y, p.z, p.w};
    const float wv[4] = {w4.x, w4.y, w4.z, w4.w};
    const float bv[4] = {b4.x, b4.y, b4.z, b4.w};
    const float kk[4] = {k4.x, k4.y, k4.z, k4.w};
    const float vv[4] = {v4.x, v4.y, v4.z, v4.w};
    const float rr[4] = {r4.x, r4.y, r4.z, r4.w};

    float ok[4], ov[4], orr[4];
#pragma unroll
    for (int i = 0; i < 4; i++) {
        const float cn = (cv[i] - mc) * rc * wv[i] + bv[i];
        const float pn = has_prev ? ((pv[i] - mp) * rp * wv[i] + bv[i]) : 0.f;
        ok[i]  = cn * kk[i] + pn * (1.0f - kk[i]);
        ov[i]  = cn * vv[i] + pn * (1.0f - vv[i]);
        orr[i] = cn * rr[i] + pn * (1.0f - rr[i]);
    }

    const size_t off = (size_t)row * D_MODEL + 4 * tid;
    unsigned short h[4], l[4];
#pragma unroll
    for (int i = 0; i < 4; i++) split_bf16(ok[i], h[i], l[i]);
    *(uint2*)(g_xk_h + off) = make_uint2(h[0] | ((uint32_t)h[1] << 16), h[2] | ((uint32_t)h[3] << 16));
    *(uint2*)(g_xk_l + off) = make_uint2(l[0] | ((uint32_t)l[1] << 16), l[2] | ((uint32_t)l[3] << 16));
#pragma unroll
    for (int i = 0; i < 4; i++) split_bf16(ov[i], h[i], l[i]);
    *(uint2*)(g_xv_h + off) = make_uint2(h[0] | ((uint32_t)h[1] << 16), h[2] | ((uint32_t)h[3] << 16));
    *(uint2*)(g_xv_l + off) = make_uint2(l[0] | ((uint32_t)l[1] << 16), l[2] | ((uint32_t)l[3] << 16));
#pragma unroll
    for (int i = 0; i < 4; i++) split_bf16(orr[i], h[i], l[i]);
    *(uint2*)(g_xr_h + off) = make_uint2(h[0] | ((uint32_t)h[1] << 16), h[2] | ((uint32_t)h[3] << 16));
    *(uint2*)(g_xr_l + off) = make_uint2(l[0] | ((uint32_t)l[1] << 16), l[2] | ((uint32_t)l[3] << 16));
}

// ---------------------------------------------------------------------------
// Weight conversion: fp32 -> bf16 hi/lo, all 4 matrices.
// grid (D*D/4/256, 4), 256 threads, float4 per thread.
// ---------------------------------------------------------------------------
__global__ __launch_bounds__(256)
void wconv_kernel(const float* __restrict__ Wk, const float* __restrict__ Wv,
                  const float* __restrict__ Wr, const float* __restrict__ Wo) {
    const int m = blockIdx.y;
    const float* src = (m == 0) ? Wk : (m == 1) ? Wv : (m == 2) ? Wr : Wo;
    const size_t base = (size_t)m * D_MODEL * D_MODEL;
    const int idx = blockIdx.x * 256 + threadIdx.x;       // float4 index
    const float4 w = ((const float4*)src)[idx];
    const float v[4] = {w.x, w.y, w.z, w.w};
    unsigned short h[4], l[4];
#pragma unroll
    for (int i = 0; i < 4; i++) split_bf16(v[i], h[i], l[i]);
    const size_t off = base + (size_t)idx * 4;
    *(uint2*)(g_W_h + off) = make_uint2(h[0] | ((uint32_t)h[1] << 16), h[2] | ((uint32_t)h[3] << 16));
    *(uint2*)(g_W_l + off) = make_uint2(l[0] | ((uint32_t)l[1] << 16), l[2] | ((uint32_t)l[3] << 16));
}

// ---------------------------------------------------------------------------
// Tensor-core GEMM:  C[m,n] = sum_k A[m,k] * W[n,k]   (fp32 via bf16 split-3)
// BM=BN=128, BK=32, 256 threads (8 warps, 2x4 warp grid, 64x32 warp tiles).
// cp.async 2-stage pipeline; smem rows padded to 40 bf16 (80B).
// MODE 0: C = acc ; 1: C = sigmoid(acc) ; 2: C = aux_x + aux_r * acc.
// ---------------------------------------------------------------------------
#define PITCH       40
#define TILE_BYTES  (128 * PITCH * 2)   // 10240
#define STAGE_BYTES (4 * TILE_BYTES)    // 40960
#define NKT         (D_MODEL / 32)      // 32

template <int MODE>
__device__ __forceinline__
void gemm_body(const __nv_bfloat16* __restrict__ Ah, const __nv_bfloat16* __restrict__ Al,
               const __nv_bfloat16* __restrict__ Bh, const __nv_bfloat16* __restrict__ Bl,
               float* __restrict__ C,
               const float* __restrict__ aux_r, const float* __restrict__ aux_x) {
    extern __shared__ char dynsmem[];
    const uint32_t sbase = (uint32_t)__cvta_generic_to_shared(dynsmem);

    const int tid = threadIdx.x;
    const int m0 = blockIdx.y * 128;
    const int n0 = blockIdx.x * 128;

    // cp.async mapping: 512 16B-chunks per tile; thread covers chunks tid, tid+256.
    const int r0 = tid >> 2,            q0 = (tid & 3) * 8;
    const int r1 = (tid + 256) >> 2,    q1 = (tid & 3) * 8;   // (tid+256)&3 == tid&3

    const __nv_bfloat16* gA_h = Ah + (size_t)m0 * D_MODEL;
    const __nv_bfloat16* gA_l = Al + (size_t)m0 * D_MODEL;
    const __nv_bfloat16* gB_h = Bh + (size_t)n0 * D_MODEL;
    const __nv_bfloat16* gB_l = Bl + (size_t)n0 * D_MODEL;

#define ISSUE_STAGE(KT, STG)                                                          \
    do {                                                                              \
        const uint32_t st_ = sbase + (STG) * STAGE_BYTES;                             \
        const int kc_ = (KT) * 32;                                                    \
        cp16(st_ + 0 * TILE_BYTES + (r0 * PITCH + q0) * 2, gA_h + (size_t)r0 * D_MODEL + kc_ + q0); \
        cp16(st_ + 0 * TILE_BYTES + (r1 * PITCH + q1) * 2, gA_h + (size_t)r1 * D_MODEL + kc_ + q1); \
        cp16(st_ + 1 * TILE_BYTES + (r0 * PITCH + q0) * 2, gA_l + (size_t)r0 * D_MODEL + kc_ + q0); \
        cp16(st_ + 1 * TILE_BYTES + (r1 * PITCH + q1) * 2, gA_l + (size_t)r1 * D_MODEL + kc_ + q1); \
        cp16(st_ + 2 * TILE_BYTES + (r0 * PITCH + q0) * 2, gB_h + (size_t)r0 * D_MODEL + kc_ + q0); \
        cp16(st_ + 2 * TILE_BYTES + (r1 * PITCH + q1) * 2, gB_h + (size_t)r1 * D_MODEL + kc_ + q1); \
        cp16(st_ + 3 * TILE_BYTES + (r0 * PITCH + q0) * 2, gB_l + (size_t)r0 * D_MODEL + kc_ + q0); \
        cp16(st_ + 3 * TILE_BYTES + (r1 * PITCH + q1) * 2, gB_l + (size_t)r1 * D_MODEL + kc_ + q1); \
        asm volatile("cp.async.commit_group;");                                       \
    } while (0)

    const int lane = tid & 31, warp = tid >> 5;
    const int wm = (warp & 1) * 64;   // warp m-offset
    const int wn = (warp >> 1) * 32;  // warp n-offset

    // ldmatrix base offsets (elements)
    const int a_row = wm + (lane & 15);
    const int a_col = 8 * (lane >> 4);
    const int b_row = wn + (lane & 7) + 8 * (lane >> 4);
    const int b_col = 8 * ((lane >> 3) & 1);

    float acc[4][4][4];
#pragma unroll
    for (int i = 0; i < 4; i++)
#pragma unroll
        for (int j = 0; j < 4; j++)
#pragma unroll
            for (int e = 0; e < 4; e++) acc[i][j][e] = 0.f;

    ISSUE_STAGE(0, 0);

    for (int kt = 0; kt < NKT; kt++) {
        const int cur = kt & 1;
        if (kt < NKT - 1) {
            ISSUE_STAGE(kt + 1, cur ^ 1);
            asm volatile("cp.async.wait_group 1;");
        } else {
            asm volatile("cp.async.wait_group 0;");
        }
        __syncthreads();

        const uint32_t st  = sbase + cur * STAGE_BYTES;
        const uint32_t aAh = st + 0 * TILE_BYTES;
        const uint32_t aAl = st + 1 * TILE_BYTES;
        const uint32_t aBh = st + 2 * TILE_BYTES;
        const uint32_t aBl = st + 3 * TILE_BYTES;

#pragma unroll
        for (int ks = 0; ks < 2; ks++) {
            uint32_t Afh[4][4], Afl[4][4], Bfh[2][4], Bfl[2][4];
#pragma unroll
            for (int i = 0; i < 4; i++)
                ldsm4(Afh[i], aAh + ((a_row + i * 16) * PITCH + a_col + ks * 16) * 2);
#pragma unroll
            for (int i = 0; i < 4; i++)
                ldsm4(Afl[i], aAl + ((a_row + i * 16) * PITCH + a_col + ks * 16) * 2);
#pragma unroll
            for (int j = 0; j < 2; j++)
                ldsm4(Bfh[j], aBh + ((b_row + j * 16) * PITCH + b_col + ks * 16) * 2);
#pragma unroll
            for (int j = 0; j < 2; j++)
                ldsm4(Bfl[j], aBl + ((b_row + j * 16) * PITCH + b_col + ks * 16) * 2);

            // hi*hi
#pragma unroll
            for (int i = 0; i < 4; i++)
#pragma unroll
                for (int j = 0; j < 4; j++)
                    mma16816(acc[i][j], Afh[i], Bfh[j >> 1][(j & 1) * 2], Bfh[j >> 1][(j & 1) * 2 + 1]);
            // hi*lo
#pragma unroll
            for (int i = 0; i < 4; i++)
#pragma unroll
                for (int j = 0; j < 4; j++)
                    mma16816(acc[i][j], Afh[i], Bfl[j >> 1][(j & 1) * 2], Bfl[j >> 1][(j & 1) * 2 + 1]);
            // lo*hi
#pragma unroll
            for (int i = 0; i < 4; i++)
#pragma unroll
                for (int j = 0; j < 4; j++)
                    mma16816(acc[i][j], Afl[i], Bfh[j >> 1][(j & 1) * 2], Bfh[j >> 1][(j & 1) * 2 + 1]);
        }
        __syncthreads();
    }
#undef ISSUE_STAGE

    // epilogue
#pragma unroll
    for (int i = 0; i < 4; i++) {
        const int row = m0 + wm + i * 16 + (lane >> 2);
#pragma unroll
        for (int j = 0; j < 4; j++) {
            const int col = n0 + wn + j * 8 + (lane & 3) * 2;
            float v0 = acc[i][j][0], v1 = acc[i][j][1];
            float v2 = acc[i][j][2], v3 = acc[i][j][3];
            const size_t idx0 = (size_t)row * D_MODEL + col;
            const size_t idx1 = (size_t)(row + 8) * D_MODEL + col;
            if (MODE == 1) {
                v0 = 1.0f / (1.0f + expf(-v0));
                v1 = 1.0f / (1.0f + expf(-v1));
                v2 = 1.0f / (1.0f + expf(-v2));
                v3 = 1.0f / (1.0f + expf(-v3));
            } else if (MODE == 2) {
                const float2 ra = *(const float2*)(aux_r + idx0);
                const float2 xa = *(const float2*)(aux_x + idx0);
                const float2 rb = *(const float2*)(aux_r + idx1);
                const float2 xb = *(const float2*)(aux_x + idx1);
                v0 = xa.x + ra.x * v0;  v1 = xa.y + ra.y * v1;
                v2 = xb.x + rb.x * v2;  v3 = xb.y + rb.y * v3;
            }
            *(float2*)(C + idx0) = make_float2(v0, v1);
            *(float2*)(C + idx1) = make_float2(v2, v3);
        }
    }
}

// Fused k/v/r projections (z selects); r gets sigmoid.
__global__ __launch_bounds__(256)
void gemm_kvr_kernel() {
    const size_t woff = (size_t)blockIdx.z * D_MODEL * D_MODEL;
    if (blockIdx.z == 0)
        gemm_body<0>(g_xk_h, g_xk_l, g_W_h + woff, g_W_l + woff, g_k, nullptr, nullptr);
    else if (blockIdx.z == 1)
        gemm_body<0>(g_xv_h, g_xv_l, g_W_h + woff, g_W_l + woff, g_v, nullptr, nullptr);
    else
        gemm_body<1>(g_xr_h, g_xr_l, g_W_h + woff, g_W_l + woff, g_r, nullptr, nullptr);
}

// out = x + r * (S_seq @ Wo^T)
__global__ __launch_bounds__(256)
void gemm_out_kernel(float* __restrict__ out, const float* __restrict__ x) {
    const size_t wo = (size_t)3 * D_MODEL * D_MODEL;
    gemm_body<2>(g_S_h, g_S_l, g_W_h + wo, g_W_l + wo, out, g_r, x);
}

// ---------------------------------------------------------------------------
// Channel-wise linear recurrence; also emits bf16 hi/lo split of S for the
// output GEMM.  One thread per (b, d).
// ---------------------------------------------------------------------------
__global__ __launch_bounds__(256)
void scan_kernel(const float* __restrict__ decay_w,
                 float* __restrict__ S_seq, float* __restrict__ final_S) {
    const int gid = blockIdx.x * blockDim.x + threadIdx.x;
    if (gid >= BATCH * D_MODEL) return;
    const int b = gid >> 10;
    const int d = gid & 1023;
    const float dec = 1.0f / (1.0f + expf(-decay_w[d]));
    float S = 0.f;
    size_t base = ((size_t)b * SEQ) * D_MODEL + d;
#pragma unroll 4
    for (int t = 0; t < SEQ; t++) {
        const float kv = g_k[base] * g_v[base];
        S = fmaf(dec, S, kv);
        S_seq[base] = S;
        const __nv_bfloat16 h = __float2bfloat16(S);
        g_S_h[base] = h;
        g_S_l[base] = __float2bfloat16(S - __bfloat162float(h));
        base += D_MODEL;
    }
    final_S[gid] = S;
}

// ---------------------------------------------------------------------------
extern "C" void kernel_launch(void* const* d_in, const int* in_sizes, int n_in,
                              void* d_out, int out_size) {
    const float* x       = (const float*)d_in[0];
    const float* ln_w    = (const float*)d_in[1];
    const float* ln_b    = (const float*)d_in[2];
    const float* tmk     = (const float*)d_in[3];
    const float* tmv     = (const float*)d_in[4];
    const float* tmr     = (const float*)d_in[5];
    const float* decay_w = (const float*)d_in[6];
    const float* Wk      = (const float*)d_in[7];
    const float* Wv      = (const float*)d_in[8];
    const float* Wr      = (const float*)d_in[9];
    const float* Wo      = (const float*)d_in[10];

    float* out     = (float*)d_out;
    float* final_S = out + MD;
    float* S_seq   = final_S + (size_t)BATCH * D_MODEL;

    const int smem = 2 * STAGE_BYTES;   // 81920
    cudaFuncSetAttribute(gemm_kvr_kernel, cudaFuncAttributeMaxDynamicSharedMemorySize, smem);
    cudaFuncSetAttribute(gemm_out_kernel, cudaFuncAttributeMaxDynamicSharedMemorySize, smem);

    // 0) weight split (cheap; every launch for determinism)
    wconv_kernel<<<dim3(D_MODEL * D_MODEL / 4 / 256, 4), 256>>>(Wk, Wv, Wr, Wo);

    // 1) LN + token mix -> bf16 hi/lo
    prep_kernel<<<M_ROWS, 256>>>(x, ln_w, ln_b, tmk, tmv, tmr);

    // 2) k, v, r projections on tensor cores
    gemm_kvr_kernel<<<dim3(D_MODEL / 128, M_ROWS / 128, 3), 256, smem>>>();

    // 3) recurrence -> S_seq (fp32, into d_out) + final_S + S hi/lo
    scan_kernel<<<(BATCH * D_MODEL) / 256, 256>>>(decay_w, S_seq, final_S);

    // 4) out = x + r * (S_seq @ Wo^T)
    gemm_out_kernel<<<dim3(D_MODEL / 128, M_ROWS / 128), 256, smem>>>(out, x);
}